// round 5
// baseline (speedup 1.0000x reference)
#include <cuda_runtime.h>

// ---------------- problem constants ----------------
#define Bsz   64
#define Tn    256
#define Lc    20
#define WD    300
#define CDm   100
#define PDm   100
#define NF    100
#define CVv   100
#define Hh    256
#define D0r   500          // real input dim layer 0
#define DP    512          // padded K for all GEMMs
#define G4    1024         // 4*H
#define NW    2048         // 2 dirs * 4H
#define BT    (Bsz*Tn)     // 16384
#define OUTW  (2*Hh)       // 512

// ---------------- scratch (device globals; no runtime alloc allowed) ----------------
__device__ float d_x0[BT*DP];          // padded embed output
__device__ float d_x1[BT*OUTW];
__device__ float d_x2[BT*OUTW];
__device__ float d_gx[(size_t)BT*NW];  // input-projection gates (both dirs)
__device__ float d_wpad[NW*DP];        // padded w_ih0
__device__ float d_U[CVv*3*NF];        // factorized char conv table U[v][k][f]
__device__ float d_hbuf[2][2][Hh*Bsz]; // [parity][dir][hid*64 + b]
__device__ unsigned g_cnt;
__device__ unsigned g_gen;

// ---------------- U[v][k][f] = sum_c emb_char[v][c] * conv_w[f][c][k] ----------------
__global__ void u_kernel(const float* __restrict__ Ec, const float* __restrict__ cw)
{
    int v = blockIdx.x;
    int f = threadIdx.x;
    __shared__ float e[CDm];
    if (f < CDm) e[f] = Ec[v*CDm + f];
    __syncthreads();
    if (f < NF) {
        float a0 = 0.f, a1 = 0.f, a2 = 0.f;
        #pragma unroll 4
        for (int c = 0; c < CDm; c++) {
            float ev = e[c];
            const float* wp = cw + f*(CDm*3) + c*3;
            a0 += ev*wp[0]; a1 += ev*wp[1]; a2 += ev*wp[2];
        }
        d_U[v*300 +       f] = a0;
        d_U[v*300 + 100 + f] = a1;
        d_U[v*300 + 200 + f] = a2;
    }
}

// ---------------- pad w_ih0 (2048 x 500) -> (2048 x 512) ----------------
__global__ void padw_kernel(const float* __restrict__ w0)
{
    int idx = blockIdx.x*256 + threadIdx.x;
    if (idx >= NW*DP) return;
    int n = idx >> 9, k = idx & 511;
    d_wpad[idx] = (k < D0r) ? w0[n*D0r + k] : 0.f;
}

// ---------------- embeddings + factorized char conv -> d_x0 (padded) ----------------
__global__ void embed_kernel(const int* __restrict__ word, const int* __restrict__ chars,
                             const int* __restrict__ pos,  const float* __restrict__ Ew,
                             const float* __restrict__ Ep, const float* __restrict__ cb)
{
    int bt  = blockIdx.x;
    int tid = threadIdx.x;
    __shared__ int cs[Lc];
    if (tid < Lc) cs[tid] = chars[bt*Lc + tid];
    int w = word[bt];
    int p = pos[bt];
    float* xrow = d_x0 + (size_t)bt*DP;
    for (int i = tid; i < WD; i += 128)  xrow[i]       = Ew[(size_t)w*WD + i];
    for (int i = tid; i < PDm; i += 128) xrow[400 + i] = Ep[p*PDm + i];
    if (tid < DP - D0r) xrow[D0r + tid] = 0.f;
    __syncthreads();
    if (tid < NF) {
        int f = tid;
        float acc[Lc + 2];
        float bv = cb[f];
        #pragma unroll
        for (int q = 0; q < Lc + 2; q++) acc[q] = bv;
        #pragma unroll
        for (int j = 0; j < Lc; j++) {
            const float* u = d_U + cs[j]*300 + f;
            acc[j + 2] += u[0];
            acc[j + 1] += u[100];
            acc[j    ] += u[200];
        }
        float m = acc[0];
        #pragma unroll
        for (int q = 1; q < Lc + 2; q++) m = fmaxf(m, acc[q]);
        xrow[WD + f] = tanhf(m);
    }
}

// ---------------- input-projection SGEMM: C[M=16384][2048] = A[M][512] * W[2048][512]^T + bias ----------------
__global__ void __launch_bounds__(256) gemm_kernel(const float* __restrict__ A,
                                                   const float* __restrict__ W,
                                                   const float* __restrict__ bias,
                                                   float* __restrict__ C)
{
    const int K = DP;
    __shared__ float As[8][128];
    __shared__ float Bs[8][128];
    int bm = blockIdx.y * 128;
    int bn = blockIdx.x * 128;
    int tid = threadIdx.x;
    int loadRow = tid >> 1;
    int loadCol = (tid & 1) * 4;
    const float* Aptr = A + (size_t)(bm + loadRow)*K + loadCol;
    const float* Wptr = W + (size_t)(bn + loadRow)*K + loadCol;
    int tx = tid & 15, ty = tid >> 4;
    float acc[8][8];
    #pragma unroll
    for (int i = 0; i < 8; i++)
        #pragma unroll
        for (int j = 0; j < 8; j++) acc[i][j] = 0.f;

    for (int k0 = 0; k0 < K; k0 += 8) {
        float4 a4 = *(const float4*)(Aptr + k0);
        float4 b4 = *(const float4*)(Wptr + k0);
        As[loadCol+0][loadRow] = a4.x; As[loadCol+1][loadRow] = a4.y;
        As[loadCol+2][loadRow] = a4.z; As[loadCol+3][loadRow] = a4.w;
        Bs[loadCol+0][loadRow] = b4.x; Bs[loadCol+1][loadRow] = b4.y;
        Bs[loadCol+2][loadRow] = b4.z; Bs[loadCol+3][loadRow] = b4.w;
        __syncthreads();
        #pragma unroll
        for (int kk = 0; kk < 8; kk++) {
            float ar[8], br[8];
            #pragma unroll
            for (int i = 0; i < 8; i++) ar[i] = As[kk][ty*8 + i];
            #pragma unroll
            for (int j = 0; j < 8; j++) br[j] = Bs[kk][tx*8 + j];
            #pragma unroll
            for (int i = 0; i < 8; i++)
                #pragma unroll
                for (int j = 0; j < 8; j++) acc[i][j] = fmaf(ar[i], br[j], acc[i][j]);
        }
        __syncthreads();
    }
    #pragma unroll
    for (int i = 0; i < 8; i++) {
        int m = bm + ty*8 + i;
        float* crow = C + (size_t)m*NW + bn + tx*8;
        const float* brow = bias + bn + tx*8;
        #pragma unroll
        for (int j4 = 0; j4 < 8; j4 += 4) {
            float4 v;
            v.x = acc[i][j4+0] + brow[j4+0];
            v.y = acc[i][j4+1] + brow[j4+1];
            v.z = acc[i][j4+2] + brow[j4+2];
            v.w = acc[i][j4+3] + brow[j4+3];
            *(float4*)(crow + j4) = v;
        }
    }
}

// ---------------- barrier init ----------------
__global__ void barinit_kernel() { g_cnt = 0; g_gen = 0; }

__device__ __forceinline__ void gridbar(unsigned &lgen)
{
    __syncthreads();
    if (threadIdx.x == 0) {
        __threadfence();
        unsigned v = atomicAdd(&g_cnt, 1);
        if (v == gridDim.x - 1) {
            atomicExch(&g_cnt, 0);
            __threadfence();
            atomicExch(&g_gen, lgen + 1);
        } else {
            volatile unsigned* vg = &g_gen;
            while (*vg <= lgen) { }
        }
    }
    lgen++;
    __syncthreads();
}

// ---------------- persistent BiLSTM recurrence (one launch per layer) ----------------
// grid = 128 blocks (2 dirs x 64 hidden-chunks of 4), 256 threads, all co-resident.
#define SMEM_REC ((Hh*Bsz + 16*Hh + Bsz*16) * 4)

__global__ void __launch_bounds__(256, 1)
recur_kernel(const float* __restrict__ gx, const float* __restrict__ whh,
             const float* __restrict__ mask, float* __restrict__ out)
{
    extern __shared__ float smem[];
    float* h_s = smem;               // [hid*64 + b], 16384 floats
    float* w_s = smem + Hh*Bsz;      // [r][k], 16*256 floats
    float* g_s = w_s + 16*Hh;        // [b][r], 64*16 floats
    int tid = threadIdx.x;
    int d   = blockIdx.x >> 6;
    int blk = blockIdx.x & 63;
    int j0  = blk * 4;

    // load this block's 16 recurrent-weight rows (rows g*H + j0 + jj)
    for (int idx = tid; idx < 16*Hh; idx += 256) {
        int r = idx >> 8, k = idx & 255;
        int gate = r >> 2, jj = r & 3;
        w_s[idx] = whh[((size_t)d*G4 + gate*Hh + j0 + jj)*Hh + k];
    }
    int eb  = tid >> 2;   // batch
    int ejj = tid & 3;    // hidden within chunk
    d_hbuf[1][d][(j0 + ejj)*Bsz + eb] = 0.f;   // h0 = 0 (parity 1 read at s=0)
    float creg = 0.f;
    int bpair = tid & 31;
    int rpair = tid >> 5;
    unsigned lgen = 0;
    gridbar(lgen);

    for (int s = 0; s < Tn; s++) {
        int rp = (s & 1) ^ 1;
        int wp = s & 1;
        const float* hsrc = d_hbuf[rp][d];
        for (int i = tid*4; i < Hh*Bsz; i += 1024) {
            float4 v = __ldcg((const float4*)(hsrc + i));
            *(float4*)(h_s + i) = v;
        }
        __syncthreads();

        // gates[b][r] = sum_k h[k][b] * w[r][k]   (2b x 2r microtile, packed f32x2 FMA)
        const unsigned long long* h2 = (const unsigned long long*)h_s;
        const float* wr0 = w_s + (rpair*2)*Hh;
        const float* wr1 = wr0 + Hh;
        unsigned long long acc0 = 0ULL, acc1 = 0ULL;
        #pragma unroll 8
        for (int k = 0; k < Hh; k++) {
            unsigned long long hv = h2[k*32 + bpair];
            unsigned w0u = __float_as_uint(wr0[k]);
            unsigned w1u = __float_as_uint(wr1[k]);
            unsigned long long w00, w11;
            asm("mov.b64 %0, {%1, %1};" : "=l"(w00) : "r"(w0u));
            asm("mov.b64 %0, {%1, %1};" : "=l"(w11) : "r"(w1u));
            asm("fma.rn.f32x2 %0, %1, %2, %0;" : "+l"(acc0) : "l"(hv), "l"(w00));
            asm("fma.rn.f32x2 %0, %1, %2, %0;" : "+l"(acc1) : "l"(hv), "l"(w11));
        }
        int b0 = bpair*2, r0 = rpair*2;
        g_s[(b0  )*16 + r0  ] = __uint_as_float((unsigned)acc0);
        g_s[(b0+1)*16 + r0  ] = __uint_as_float((unsigned)(acc0 >> 32));
        g_s[(b0  )*16 + r0+1] = __uint_as_float((unsigned)acc1);
        g_s[(b0+1)*16 + r0+1] = __uint_as_float((unsigned)(acc1 >> 32));
        __syncthreads();

        // elementwise LSTM update (thread owns (eb, j0+ejj))
        int t = d ? (Tn - 1 - s) : s;
        const float* gxr = gx + ((size_t)(eb*Tn + t))*NW + d*G4 + j0 + ejj;
        float xi = g_s[eb*16 +      ejj] + gxr[0];
        float xf = g_s[eb*16 +  4 + ejj] + gxr[Hh];
        float xg = g_s[eb*16 +  8 + ejj] + gxr[2*Hh];
        float xo = g_s[eb*16 + 12 + ejj] + gxr[3*Hh];
        float ig = 1.f/(1.f + __expf(-xi));
        float fg = 1.f/(1.f + __expf(-xf));
        float og = 1.f/(1.f + __expf(-xo));
        float gg = tanhf(xg);
        float cn = fg*creg + ig*gg;
        float hn = og*tanhf(cn);
        float m  = mask[eb*Tn + t];
        float hp = h_s[(j0 + ejj)*Bsz + eb];
        hn = m*hn + (1.f - m)*hp;
        cn = m*cn + (1.f - m)*creg;
        creg = cn;
        d_hbuf[wp][d][(j0 + ejj)*Bsz + eb] = hn;
        out[((size_t)(eb*Tn + t))*OUTW + d*Hh + j0 + ejj] = hn;
        gridbar(lgen);
    }
}

// ---------------- launch ----------------
extern "C" void kernel_launch(void* const* d_in, const int* in_sizes, int n_in,
                              void* d_out, int out_size)
{
    const int*   in_word  = (const int*)  d_in[0];
    const int*   in_char  = (const int*)  d_in[1];
    const int*   in_pos   = (const int*)  d_in[2];
    const float* mask     = (const float*)d_in[3];
    const float* emb_word = (const float*)d_in[4];
    const float* emb_char = (const float*)d_in[5];
    const float* emb_pos  = (const float*)d_in[6];
    const float* conv_w   = (const float*)d_in[7];
    const float* conv_b   = (const float*)d_in[8];
    const float* w_ih0    = (const float*)d_in[9];
    const float* w_hh0    = (const float*)d_in[10];
    const float* b0       = (const float*)d_in[11];
    const float* w_ih1    = (const float*)d_in[12];
    const float* w_hh1    = (const float*)d_in[13];
    const float* b1       = (const float*)d_in[14];
    const float* w_ih2    = (const float*)d_in[15];
    const float* w_hh2    = (const float*)d_in[16];
    const float* b2       = (const float*)d_in[17];
    float* out = (float*)d_out;

    cudaFuncSetAttribute(recur_kernel, cudaFuncAttributeMaxDynamicSharedMemorySize, SMEM_REC);

    void *px0, *px1, *px2, *pgx, *pwpad;
    cudaGetSymbolAddress(&px0,  d_x0);
    cudaGetSymbolAddress(&px1,  d_x1);
    cudaGetSymbolAddress(&px2,  d_x2);
    cudaGetSymbolAddress(&pgx,  d_gx);
    cudaGetSymbolAddress(&pwpad, d_wpad);

    // embeddings
    u_kernel<<<CVv, 128>>>(emb_char, conv_w);
    padw_kernel<<<(NW*DP + 255)/256, 256>>>(w_ih0);
    embed_kernel<<<BT, 128>>>(in_word, in_char, in_pos, emb_word, emb_pos, conv_b);

    dim3 ggrid(NW/128, BT/128);

    // layer 0
    gemm_kernel<<<ggrid, 256>>>((const float*)px0, (const float*)pwpad, b0, (float*)pgx);
    barinit_kernel<<<1, 1>>>();
    recur_kernel<<<128, 256, SMEM_REC>>>((const float*)pgx, w_hh0, mask, (float*)px1);

    // layer 1
    gemm_kernel<<<ggrid, 256>>>((const float*)px1, w_ih1, b1, (float*)pgx);
    barinit_kernel<<<1, 1>>>();
    recur_kernel<<<128, 256, SMEM_REC>>>((const float*)pgx, w_hh1, mask, (float*)px2);

    // layer 2
    gemm_kernel<<<ggrid, 256>>>((const float*)px2, w_ih2, b2, (float*)pgx);
    barinit_kernel<<<1, 1>>>();
    recur_kernel<<<128, 256, SMEM_REC>>>((const float*)pgx, w_hh2, mask, out);
}

// round 6
// speedup vs baseline: 1.0874x; 1.0874x over previous
#include <cuda_runtime.h>

typedef unsigned long long ull;

// ---------------- problem constants ----------------
#define Bsz   64
#define Tn    256
#define Lc    20
#define WD    300
#define CDm   100
#define PDm   100
#define NF    100
#define CVv   100
#define Hh    256
#define D0r   500          // real input dim layer 0
#define DP    512          // padded K for all GEMMs
#define G4    1024         // 4*H
#define NW    2048         // 2 dirs * 4H
#define BT    (Bsz*Tn)     // 16384
#define OUTW  (2*Hh)       // 512

#define DUP64(dst, s)   asm("mov.b64 %0, {%1, %1};" : "=l"(dst) : "r"(__float_as_uint(s)))
#define FMA2(acc, a, b) asm("fma.rn.f32x2 %0, %1, %2, %0;" : "+l"(acc) : "l"(a), "l"(b))
#define ADD2(acc, a)    asm("add.rn.f32x2 %0, %1, %0;" : "+l"(acc) : "l"(a))

// ---------------- scratch (device globals; no runtime alloc allowed) ----------------
__device__ float d_x0[BT*DP];          // padded embed output
__device__ float d_x1[BT*OUTW];
__device__ float d_x2[BT*OUTW];
__device__ float d_gx[(size_t)BT*NW];  // input-projection gates (both dirs)
__device__ float d_wpad[NW*DP];        // padded w_ih0
__device__ float d_U[CVv*3*NF];        // factorized char conv table U[v][k][f]
__device__ float d_hbuf[2][2][Hh*Bsz]; // [parity][dir][hid*64 + b]
__device__ unsigned g_cnt2[2];
__device__ unsigned g_gen2[2];

// ---------------- U[v][k][f] = sum_c emb_char[v][c] * conv_w[f][c][k] ----------------
__global__ void u_kernel(const float* __restrict__ Ec, const float* __restrict__ cw)
{
    int v = blockIdx.x;
    int f = threadIdx.x;
    __shared__ float e[CDm];
    if (f < CDm) e[f] = Ec[v*CDm + f];
    __syncthreads();
    if (f < NF) {
        float a0 = 0.f, a1 = 0.f, a2 = 0.f;
        #pragma unroll 4
        for (int c = 0; c < CDm; c++) {
            float ev = e[c];
            const float* wp = cw + f*(CDm*3) + c*3;
            a0 += ev*wp[0]; a1 += ev*wp[1]; a2 += ev*wp[2];
        }
        d_U[v*300 +       f] = a0;
        d_U[v*300 + 100 + f] = a1;
        d_U[v*300 + 200 + f] = a2;
    }
}

// ---------------- pad w_ih0 (2048 x 500) -> (2048 x 512) ----------------
__global__ void padw_kernel(const float* __restrict__ w0)
{
    int idx = blockIdx.x*256 + threadIdx.x;
    if (idx >= NW*DP) return;
    int n = idx >> 9, k = idx & 511;
    d_wpad[idx] = (k < D0r) ? w0[n*D0r + k] : 0.f;
}

// ---------------- embeddings + factorized char conv -> d_x0 (padded) ----------------
__global__ void embed_kernel(const int* __restrict__ word, const int* __restrict__ chars,
                             const int* __restrict__ pos,  const float* __restrict__ Ew,
                             const float* __restrict__ Ep, const float* __restrict__ cb)
{
    int bt  = blockIdx.x;
    int tid = threadIdx.x;
    __shared__ int cs[Lc];
    if (tid < Lc) cs[tid] = chars[bt*Lc + tid];
    int w = word[bt];
    int p = pos[bt];
    float* xrow = d_x0 + (size_t)bt*DP;
    for (int i = tid; i < WD; i += 128)  xrow[i]       = Ew[(size_t)w*WD + i];
    for (int i = tid; i < PDm; i += 128) xrow[400 + i] = Ep[p*PDm + i];
    if (tid < DP - D0r) xrow[D0r + tid] = 0.f;
    __syncthreads();
    if (tid < NF) {
        int f = tid;
        float acc[Lc + 2];
        float bv = cb[f];
        #pragma unroll
        for (int q = 0; q < Lc + 2; q++) acc[q] = bv;
        #pragma unroll
        for (int j = 0; j < Lc; j++) {
            const float* u = d_U + cs[j]*300 + f;
            acc[j + 2] += u[0];
            acc[j + 1] += u[100];
            acc[j    ] += u[200];
        }
        float m = acc[0];
        #pragma unroll
        for (int q = 1; q < Lc + 2; q++) m = fmaxf(m, acc[q]);
        xrow[WD + f] = tanhf(m);
    }
}

// ---------------- input-projection SGEMM (FFMA2, double-buffered) ----------------
// C[16384][2048] = A[16384][512] * W[2048][512]^T + bias
__global__ void __launch_bounds__(256) gemm_kernel(const float* __restrict__ A,
                                                   const float* __restrict__ W,
                                                   const float* __restrict__ bias,
                                                   float* __restrict__ C)
{
    __shared__ __align__(16) float As[2][8][128];
    __shared__ __align__(16) float Bs[2][8][128];
    int bm = blockIdx.y * 128;
    int bn = blockIdx.x * 128;
    int tid = threadIdx.x;
    int loadRow = tid >> 1;
    int loadCol = (tid & 1) * 4;
    const float* Aptr = A + (size_t)(bm + loadRow)*DP + loadCol;
    const float* Wptr = W + (size_t)(bn + loadRow)*DP + loadCol;
    int tx = tid & 15, ty = tid >> 4;

    ull acc[8][4];
    #pragma unroll
    for (int i = 0; i < 8; i++)
        #pragma unroll
        for (int j = 0; j < 4; j++) acc[i][j] = 0ULL;

    float4 a4 = *(const float4*)Aptr;
    float4 b4 = *(const float4*)Wptr;
    int buf = 0;

    for (int k0 = 0; k0 < DP; k0 += 8) {
        As[buf][loadCol+0][loadRow] = a4.x; As[buf][loadCol+1][loadRow] = a4.y;
        As[buf][loadCol+2][loadRow] = a4.z; As[buf][loadCol+3][loadRow] = a4.w;
        Bs[buf][loadCol+0][loadRow] = b4.x; Bs[buf][loadCol+1][loadRow] = b4.y;
        Bs[buf][loadCol+2][loadRow] = b4.z; Bs[buf][loadCol+3][loadRow] = b4.w;
        __syncthreads();
        if (k0 + 8 < DP) {
            a4 = *(const float4*)(Aptr + k0 + 8);
            b4 = *(const float4*)(Wptr + k0 + 8);
        }
        #pragma unroll
        for (int kk = 0; kk < 8; kk++) {
            ull br[4];
            #pragma unroll
            for (int j = 0; j < 4; j++)
                br[j] = *(const ull*)&Bs[buf][kk][tx*8 + 2*j];
            #pragma unroll
            for (int i = 0; i < 8; i++) {
                ull ad;
                DUP64(ad, As[buf][kk][ty*8 + i]);
                #pragma unroll
                for (int j = 0; j < 4; j++) FMA2(acc[i][j], ad, br[j]);
            }
        }
        buf ^= 1;
    }
    #pragma unroll
    for (int i = 0; i < 8; i++) {
        int m = bm + ty*8 + i;
        float* crow = C + (size_t)m*NW + bn + tx*8;
        const ull* bb = (const ull*)(bias + bn + tx*8);
        #pragma unroll
        for (int j = 0; j < 4; j++) {
            ull s = acc[i][j];
            ADD2(s, bb[j]);
            *(ull*)(crow + 2*j) = s;
        }
    }
}

// ---------------- barrier init ----------------
__global__ void barinit_kernel() { g_cnt2[0] = 0; g_cnt2[1] = 0; g_gen2[0] = 0; g_gen2[1] = 0; }

__device__ __forceinline__ void gridbar_dir(int d, unsigned &lgen)
{
    __syncthreads();
    if (threadIdx.x == 0) {
        __threadfence();
        unsigned v = atomicAdd(&g_cnt2[d], 1);
        if (v == 63) {
            atomicExch(&g_cnt2[d], 0);
            __threadfence();
            atomicExch(&g_gen2[d], lgen + 1);
        } else {
            volatile unsigned* vg = &g_gen2[d];
            while (*vg <= lgen) { }
        }
    }
    lgen++;
    __syncthreads();
}

// ---------------- persistent BiLSTM recurrence (one launch per layer) ----------------
// grid = 128 blocks (2 dirs x 64 hidden-chunks of 4 units), 256 threads, all co-resident.
// Thread tile: 4 batches x 4 gate-rows, k split 4 ways with smem reduction.
// tid = jj*64 + ks*16 + bg  (jj: hidden unit within chunk, ks: k-split, bg: batch group)
#define SMEM_REC ((16384 + 4096 + 3072) * 4)

__global__ void __launch_bounds__(256, 1)
recur_kernel(const float* __restrict__ gx, const float* __restrict__ whh,
             const float* __restrict__ mask, float* __restrict__ out)
{
    extern __shared__ __align__(16) float smem[];
    float* h_s   = smem;            // [k][b]  256*64
    float* w_s   = smem + 16384;    // [k][jj][gate]  256*16
    ull*   redu  = (ull*)(smem + 16384 + 4096);  // [g*2+p][192]

    int tid = threadIdx.x;
    int d   = blockIdx.x >> 6;
    int blk = blockIdx.x & 63;
    int j0  = blk * 4;
    int bg  = tid & 15;
    int ks  = (tid >> 4) & 3;
    int jj  = tid >> 6;
    int b0  = bg * 4;
    int kbase = ks * 64;

    // load recurrent weights into smem: w_s[k*16 + jje*4 + gate]
    for (int e = tid; e < 4096; e += 256) {
        int gate = e & 3, jje = (e >> 2) & 3, k = e >> 4;
        w_s[e] = whh[((size_t)d*G4 + gate*Hh + j0 + jje)*Hh + k];
    }
    // zero initial h (parity 1) for this block's 4 hidden units
    d_hbuf[1][d][(j0 + (tid >> 6))*Bsz + (tid & 63)] = 0.f;

    float creg[4] = {0.f, 0.f, 0.f, 0.f};
    unsigned lgen = 0;
    gridbar_dir(d, lgen);

    for (int s = 0; s < Tn; s++) {
        int rp = (s & 1) ^ 1;
        int wp = s & 1;
        int t  = d ? (Tn - 1 - s) : s;

        // prefetch gx + mask for the elementwise phase (overlaps the GEMM below)
        float gxv[4][4];
        float mv[4];
        if (ks == 0) {
            #pragma unroll
            for (int bb = 0; bb < 4; bb++) {
                const float* p = gx + ((size_t)((b0 + bb)*Tn + t))*NW + d*G4 + j0 + jj;
                gxv[bb][0] = __ldg(p);
                gxv[bb][1] = __ldg(p + Hh);
                gxv[bb][2] = __ldg(p + 2*Hh);
                gxv[bb][3] = __ldg(p + 3*Hh);
                mv[bb] = __ldg(mask + (b0 + bb)*Tn + t);
            }
        }

        // reload h (prev step, all 256 hidden units) into smem
        const float* hsrc = d_hbuf[rp][d];
        #pragma unroll
        for (int i = 0; i < 16; i++) {
            int idx = (i*256 + tid)*4;
            *(float4*)(h_s + idx) = __ldcg((const float4*)(hsrc + idx));
        }
        __syncthreads();

        // partial GEMM over this thread's 64 k values: acc[gate][bpair]
        ull acc[4][2];
        #pragma unroll
        for (int g = 0; g < 4; g++) { acc[g][0] = 0ULL; acc[g][1] = 0ULL; }

        #pragma unroll 4
        for (int kk = 0; kk < 64; kk++) {
            int k = kbase + kk;
            ulonglong2 hv = *(const ulonglong2*)(h_s + k*64 + b0);
            float4 wv = *(const float4*)(w_s + k*16 + jj*4);
            ull wd;
            DUP64(wd, wv.x); FMA2(acc[0][0], hv.x, wd); FMA2(acc[0][1], hv.y, wd);
            DUP64(wd, wv.y); FMA2(acc[1][0], hv.x, wd); FMA2(acc[1][1], hv.y, wd);
            DUP64(wd, wv.z); FMA2(acc[2][0], hv.x, wd); FMA2(acc[2][1], hv.y, wd);
            DUP64(wd, wv.w); FMA2(acc[3][0], hv.x, wd); FMA2(acc[3][1], hv.y, wd);
        }

        // k-split reduction through smem
        if (ks != 0) {
            int base = (ks - 1)*64 + jj*16 + bg;
            #pragma unroll
            for (int g = 0; g < 4; g++) {
                redu[(g*2 + 0)*192 + base] = acc[g][0];
                redu[(g*2 + 1)*192 + base] = acc[g][1];
            }
        }
        __syncthreads();

        if (ks == 0) {
            int base = jj*16 + bg;
            #pragma unroll
            for (int sp = 0; sp < 3; sp++) {
                #pragma unroll
                for (int g = 0; g < 4; g++) {
                    ADD2(acc[g][0], redu[(g*2 + 0)*192 + sp*64 + base]);
                    ADD2(acc[g][1], redu[(g*2 + 1)*192 + sp*64 + base]);
                }
            }
            // elementwise LSTM update for 4 batches of hidden unit j0+jj
            float4 hpv4 = *(const float4*)(h_s + (j0 + jj)*64 + b0);
            float hpv[4] = {hpv4.x, hpv4.y, hpv4.z, hpv4.w};
            float hnew[4];
            #pragma unroll
            for (int bb = 0; bb < 4; bb++) {
                int pr = bb >> 1, hi = bb & 1;
                float gi = (hi ? __uint_as_float((unsigned)(acc[0][pr] >> 32))
                              : __uint_as_float((unsigned)acc[0][pr])) + gxv[bb][0];
                float gf = (hi ? __uint_as_float((unsigned)(acc[1][pr] >> 32))
                              : __uint_as_float((unsigned)acc[1][pr])) + gxv[bb][1];
                float gg = (hi ? __uint_as_float((unsigned)(acc[2][pr] >> 32))
                              : __uint_as_float((unsigned)acc[2][pr])) + gxv[bb][2];
                float go = (hi ? __uint_as_float((unsigned)(acc[3][pr] >> 32))
                              : __uint_as_float((unsigned)acc[3][pr])) + gxv[bb][3];
                float ig = 1.f/(1.f + __expf(-gi));
                float fg = 1.f/(1.f + __expf(-gf));
                float og = 1.f/(1.f + __expf(-go));
                float gt = tanhf(gg);
                float cn = fg*creg[bb] + ig*gt;
                float hn = og*tanhf(cn);
                float m  = mv[bb];
                hn = m*hn + (1.f - m)*hpv[bb];
                cn = m*cn + (1.f - m)*creg[bb];
                creg[bb] = cn;
                hnew[bb] = hn;
                out[((size_t)((b0 + bb)*Tn + t))*OUTW + d*Hh + j0 + jj] = hn;
            }
            *(float4*)(&d_hbuf[wp][d][(j0 + jj)*64 + b0]) =
                make_float4(hnew[0], hnew[1], hnew[2], hnew[3]);
            __threadfence();
        }
        gridbar_dir(d, lgen);
    }
}

// ---------------- launch ----------------
extern "C" void kernel_launch(void* const* d_in, const int* in_sizes, int n_in,
                              void* d_out, int out_size)
{
    const int*   in_word  = (const int*)  d_in[0];
    const int*   in_char  = (const int*)  d_in[1];
    const int*   in_pos   = (const int*)  d_in[2];
    const float* mask     = (const float*)d_in[3];
    const float* emb_word = (const float*)d_in[4];
    const float* emb_char = (const float*)d_in[5];
    const float* emb_pos  = (const float*)d_in[6];
    const float* conv_w   = (const float*)d_in[7];
    const float* conv_b   = (const float*)d_in[8];
    const float* w_ih0    = (const float*)d_in[9];
    const float* w_hh0    = (const float*)d_in[10];
    const float* b0       = (const float*)d_in[11];
    const float* w_ih1    = (const float*)d_in[12];
    const float* w_hh1    = (const float*)d_in[13];
    const float* b1       = (const float*)d_in[14];
    const float* w_ih2    = (const float*)d_in[15];
    const float* w_hh2    = (const float*)d_in[16];
    const float* b2       = (const float*)d_in[17];
    float* out = (float*)d_out;

    cudaFuncSetAttribute(recur_kernel, cudaFuncAttributeMaxDynamicSharedMemorySize, SMEM_REC);

    void *px0, *px1, *px2, *pgx, *pwpad;
    cudaGetSymbolAddress(&px0,  d_x0);
    cudaGetSymbolAddress(&px1,  d_x1);
    cudaGetSymbolAddress(&px2,  d_x2);
    cudaGetSymbolAddress(&pgx,  d_gx);
    cudaGetSymbolAddress(&pwpad, d_wpad);

    // embeddings
    u_kernel<<<CVv, 128>>>(emb_char, conv_w);
    padw_kernel<<<(NW*DP + 255)/256, 256>>>(w_ih0);
    embed_kernel<<<BT, 128>>>(in_word, in_char, in_pos, emb_word, emb_pos, conv_b);

    dim3 ggrid(NW/128, BT/128);

    // layer 0
    gemm_kernel<<<ggrid, 256>>>((const float*)px0, (const float*)pwpad, b0, (float*)pgx);
    barinit_kernel<<<1, 1>>>();
    recur_kernel<<<128, 256, SMEM_REC>>>((const float*)pgx, w_hh0, mask, (float*)px1);

    // layer 1
    gemm_kernel<<<ggrid, 256>>>((const float*)px1, w_ih1, b1, (float*)pgx);
    barinit_kernel<<<1, 1>>>();
    recur_kernel<<<128, 256, SMEM_REC>>>((const float*)pgx, w_hh1, mask, (float*)px2);

    // layer 2
    gemm_kernel<<<ggrid, 256>>>((const float*)px2, w_ih2, b2, (float*)pgx);
    barinit_kernel<<<1, 1>>>();
    recur_kernel<<<128, 256, SMEM_REC>>>((const float*)pgx, w_hh2, mask, out);
}

// round 7
// speedup vs baseline: 1.1991x; 1.1027x over previous
#include <cuda_runtime.h>

typedef unsigned long long ull;

// ---------------- problem constants ----------------
#define Bsz   64
#define Tn    256
#define Lc    20
#define WD    300
#define CDm   100
#define PDm   100
#define NF    100
#define CVv   100
#define Hh    256
#define D0r   500          // real input dim layer 0
#define DP    512          // padded K for all GEMMs
#define G4    1024         // 4*H
#define NW    2048         // 2 dirs * 4H
#define BT    (Bsz*Tn)     // 16384
#define OUTW  (2*Hh)       // 512

#define DUP64(dst, s)   asm("mov.b64 %0, {%1, %1};" : "=l"(dst) : "r"(__float_as_uint(s)))
#define FMA2(acc, a, b) asm("fma.rn.f32x2 %0, %1, %2, %0;" : "+l"(acc) : "l"(a), "l"(b))
#define ADD2(acc, a)    asm("add.rn.f32x2 %0, %1, %0;" : "+l"(acc) : "l"(a))

// ---------------- scratch (device globals; no runtime alloc allowed) ----------------
__device__ float d_x0[BT*DP];          // padded embed output
__device__ float d_x1[BT*OUTW];
__device__ float d_x2[BT*OUTW];
__device__ float d_gx[(size_t)BT*NW];  // input-projection gates (both dirs)
__device__ float d_wpad[NW*DP];        // padded w_ih0
__device__ float d_U[CVv*3*NF];        // factorized char conv table U[v][k][f]
__device__ float d_hbuf[2][2][Hh*Bsz]; // [parity][dir][hid*64 + b]
__device__ unsigned g_cnt2[2];
__device__ unsigned g_gen2[2];

// ---------------- U[v][k][f] = sum_c emb_char[v][c] * conv_w[f][c][k] ----------------
__global__ void u_kernel(const float* __restrict__ Ec, const float* __restrict__ cw)
{
    int v = blockIdx.x;
    int f = threadIdx.x;
    __shared__ float e[CDm];
    if (f < CDm) e[f] = Ec[v*CDm + f];
    __syncthreads();
    if (f < NF) {
        float a0 = 0.f, a1 = 0.f, a2 = 0.f;
        #pragma unroll 4
        for (int c = 0; c < CDm; c++) {
            float ev = e[c];
            const float* wp = cw + f*(CDm*3) + c*3;
            a0 += ev*wp[0]; a1 += ev*wp[1]; a2 += ev*wp[2];
        }
        d_U[v*300 +       f] = a0;
        d_U[v*300 + 100 + f] = a1;
        d_U[v*300 + 200 + f] = a2;
    }
}

// ---------------- pad w_ih0 (2048 x 500) -> (2048 x 512) ----------------
__global__ void padw_kernel(const float* __restrict__ w0)
{
    int idx = blockIdx.x*256 + threadIdx.x;
    if (idx >= NW*DP) return;
    int n = idx >> 9, k = idx & 511;
    d_wpad[idx] = (k < D0r) ? w0[n*D0r + k] : 0.f;
}

// ---------------- embeddings + factorized char conv -> d_x0 (padded) ----------------
__global__ void embed_kernel(const int* __restrict__ word, const int* __restrict__ chars,
                             const int* __restrict__ pos,  const float* __restrict__ Ew,
                             const float* __restrict__ Ep, const float* __restrict__ cb)
{
    int bt  = blockIdx.x;
    int tid = threadIdx.x;
    __shared__ int cs[Lc];
    if (tid < Lc) cs[tid] = chars[bt*Lc + tid];
    int w = word[bt];
    int p = pos[bt];
    float* xrow = d_x0 + (size_t)bt*DP;
    for (int i = tid; i < WD; i += 128)  xrow[i]       = Ew[(size_t)w*WD + i];
    for (int i = tid; i < PDm; i += 128) xrow[400 + i] = Ep[p*PDm + i];
    if (tid < DP - D0r) xrow[D0r + tid] = 0.f;
    __syncthreads();
    if (tid < NF) {
        int f = tid;
        float acc[Lc + 2];
        float bv = cb[f];
        #pragma unroll
        for (int q = 0; q < Lc + 2; q++) acc[q] = bv;
        #pragma unroll
        for (int j = 0; j < Lc; j++) {
            const float* u = d_U + cs[j]*300 + f;
            acc[j + 2] += u[0];
            acc[j + 1] += u[100];
            acc[j    ] += u[200];
        }
        float m = acc[0];
        #pragma unroll
        for (int q = 1; q < Lc + 2; q++) m = fmaxf(m, acc[q]);
        xrow[WD + f] = tanhf(m);
    }
}

// ---------------- input-projection SGEMM (FFMA2, double-buffered, LDS.128) ----------------
// C[16384][2048] = A[16384][512] * W[2048][512]^T + bias
__global__ void __launch_bounds__(256) gemm_kernel(const float* __restrict__ A,
                                                   const float* __restrict__ W,
                                                   const float* __restrict__ bias,
                                                   float* __restrict__ C)
{
    __shared__ __align__(16) float As[2][8][128];
    __shared__ __align__(16) float Bs[2][8][128];
    int bm = blockIdx.y * 128;
    int bn = blockIdx.x * 128;
    int tid = threadIdx.x;
    int loadRow = tid >> 1;
    int loadCol = (tid & 1) * 4;
    const float* Aptr = A + (size_t)(bm + loadRow)*DP + loadCol;
    const float* Wptr = W + (size_t)(bn + loadRow)*DP + loadCol;
    int tx = tid & 15, ty = tid >> 4;

    ull acc[8][4];
    #pragma unroll
    for (int i = 0; i < 8; i++)
        #pragma unroll
        for (int j = 0; j < 4; j++) acc[i][j] = 0ULL;

    float4 a4 = *(const float4*)Aptr;
    float4 b4 = *(const float4*)Wptr;
    int buf = 0;

    for (int k0 = 0; k0 < DP; k0 += 8) {
        As[buf][loadCol+0][loadRow] = a4.x; As[buf][loadCol+1][loadRow] = a4.y;
        As[buf][loadCol+2][loadRow] = a4.z; As[buf][loadCol+3][loadRow] = a4.w;
        Bs[buf][loadCol+0][loadRow] = b4.x; Bs[buf][loadCol+1][loadRow] = b4.y;
        Bs[buf][loadCol+2][loadRow] = b4.z; Bs[buf][loadCol+3][loadRow] = b4.w;
        __syncthreads();
        if (k0 + 8 < DP) {
            a4 = *(const float4*)(Aptr + k0 + 8);
            b4 = *(const float4*)(Wptr + k0 + 8);
        }
        #pragma unroll
        for (int kk = 0; kk < 8; kk++) {
            ulonglong2 bq0 = *(const ulonglong2*)&Bs[buf][kk][tx*8];
            ulonglong2 bq1 = *(const ulonglong2*)&Bs[buf][kk][tx*8 + 4];
            float4 aq0 = *(const float4*)&As[buf][kk][ty*8];
            float4 aq1 = *(const float4*)&As[buf][kk][ty*8 + 4];
            ull ad;
            DUP64(ad, aq0.x);
            FMA2(acc[0][0], ad, bq0.x); FMA2(acc[0][1], ad, bq0.y);
            FMA2(acc[0][2], ad, bq1.x); FMA2(acc[0][3], ad, bq1.y);
            DUP64(ad, aq0.y);
            FMA2(acc[1][0], ad, bq0.x); FMA2(acc[1][1], ad, bq0.y);
            FMA2(acc[1][2], ad, bq1.x); FMA2(acc[1][3], ad, bq1.y);
            DUP64(ad, aq0.z);
            FMA2(acc[2][0], ad, bq0.x); FMA2(acc[2][1], ad, bq0.y);
            FMA2(acc[2][2], ad, bq1.x); FMA2(acc[2][3], ad, bq1.y);
            DUP64(ad, aq0.w);
            FMA2(acc[3][0], ad, bq0.x); FMA2(acc[3][1], ad, bq0.y);
            FMA2(acc[3][2], ad, bq1.x); FMA2(acc[3][3], ad, bq1.y);
            DUP64(ad, aq1.x);
            FMA2(acc[4][0], ad, bq0.x); FMA2(acc[4][1], ad, bq0.y);
            FMA2(acc[4][2], ad, bq1.x); FMA2(acc[4][3], ad, bq1.y);
            DUP64(ad, aq1.y);
            FMA2(acc[5][0], ad, bq0.x); FMA2(acc[5][1], ad, bq0.y);
            FMA2(acc[5][2], ad, bq1.x); FMA2(acc[5][3], ad, bq1.y);
            DUP64(ad, aq1.z);
            FMA2(acc[6][0], ad, bq0.x); FMA2(acc[6][1], ad, bq0.y);
            FMA2(acc[6][2], ad, bq1.x); FMA2(acc[6][3], ad, bq1.y);
            DUP64(ad, aq1.w);
            FMA2(acc[7][0], ad, bq0.x); FMA2(acc[7][1], ad, bq0.y);
            FMA2(acc[7][2], ad, bq1.x); FMA2(acc[7][3], ad, bq1.y);
        }
        buf ^= 1;
    }
    #pragma unroll
    for (int i = 0; i < 8; i++) {
        int m = bm + ty*8 + i;
        float* crow = C + (size_t)m*NW + bn + tx*8;
        const ull* bb = (const ull*)(bias + bn + tx*8);
        #pragma unroll
        for (int j = 0; j < 4; j++) {
            ull s = acc[i][j];
            ADD2(s, bb[j]);
            *(ull*)(crow + 2*j) = s;
        }
    }
}

// ---------------- barrier init ----------------
__global__ void barinit_kernel() { g_cnt2[0] = 0; g_cnt2[1] = 0; g_gen2[0] = 0; g_gen2[1] = 0; }

__device__ __forceinline__ void gridbar_dir(int d, unsigned &lgen)
{
    __syncthreads();
    if (threadIdx.x == 0) {
        __threadfence();   // cumulative: covers all block stores ordered by the bar.sync above
        unsigned v = atomicAdd(&g_cnt2[d], 1);
        if (v == 63) {
            atomicExch(&g_cnt2[d], 0);
            __threadfence();
            atomicExch(&g_gen2[d], lgen + 1);
        } else {
            volatile unsigned* vg = &g_gen2[d];
            while (*vg <= lgen) { }
        }
    }
    lgen++;
    __syncthreads();
}

// ---------------- persistent BiLSTM recurrence (one launch per layer) ----------------
// grid = 128 blocks (2 dirs x 64 hidden-chunks of 4 units), 256 threads, all co-resident.
// GEMM phase:  tid = jj | bg<<2 | ks<<6  (4 jj x 16 bg x 4 ks), thread tile 4b x 4g x 64k.
// Elementwise: tid = eb | ejj<<6         (64 batches x 4 units), one cell per thread.
#define SMEM_REC (65536 + 16384 + 16384)

__global__ void __launch_bounds__(256, 1)
recur_kernel(const float* __restrict__ gx, const float* __restrict__ whh,
             const float* __restrict__ mask, float* __restrict__ out)
{
    extern __shared__ __align__(16) float smem[];
    float* h_s   = smem;                       // [k][b]  256*64
    float* w_s   = smem + 16384;               // [k][jj][gate]  256*16
    ull*   redu  = (ull*)(smem + 20480);       // [ks][gate][jj][32]  (2048 ull)
    float* reduF = (float*)redu;

    int tid = threadIdx.x;
    int d   = blockIdx.x >> 6;
    int blk = blockIdx.x & 63;
    int j0  = blk * 4;

    // GEMM-phase coords
    int jj = tid & 3;
    int bg = (tid >> 2) & 15;
    int ks = tid >> 6;
    int b0 = bg * 4;
    int kbase = ks * 64;

    // elementwise coords
    int eb  = tid & 63;
    int ejj = tid >> 6;

    // load recurrent weights into smem: w_s[k*16 + jje*4 + gate]
    for (int e = tid; e < 4096; e += 256) {
        int gate = e & 3, jje = (e >> 2) & 3, k = e >> 4;
        w_s[e] = whh[((size_t)d*G4 + gate*Hh + j0 + jje)*Hh + k];
    }
    // zero initial h (parity 1)
    d_hbuf[1][d][(j0 + ejj)*Bsz + eb] = 0.f;

    float creg = 0.f;
    unsigned lgen = 0;
    gridbar_dir(d, lgen);

    for (int s = 0; s < Tn; s++) {
        int rp = (s & 1) ^ 1;
        int wp = s & 1;
        int t  = d ? (Tn - 1 - s) : s;

        // prefetch gx + mask for this thread's cell (consumed at end of step)
        const float* gp = gx + ((size_t)(eb*Tn + t))*NW + d*G4 + j0 + ejj;
        float gxi = __ldg(gp);
        float gxf = __ldg(gp + Hh);
        float gxg = __ldg(gp + 2*Hh);
        float gxo = __ldg(gp + 3*Hh);
        float mv  = __ldg(mask + eb*Tn + t);

        // reload h (prev step, all 256 hidden units) into smem
        const float* hsrc = d_hbuf[rp][d];
        #pragma unroll
        for (int i = 0; i < 16; i++) {
            int idx = (i*256 + tid)*4;
            *(float4*)(h_s + idx) = __ldcg((const float4*)(hsrc + idx));
        }
        __syncthreads();

        // partial GEMM over this thread's 64 k values: acc[gate][bpair]
        ull acc[4][2];
        #pragma unroll
        for (int g = 0; g < 4; g++) { acc[g][0] = 0ULL; acc[g][1] = 0ULL; }

        #pragma unroll 4
        for (int kk = 0; kk < 64; kk++) {
            int k = kbase + kk;
            ulonglong2 hv = *(const ulonglong2*)(h_s + k*64 + b0);
            float4 wv = *(const float4*)(w_s + k*16 + jj*4);
            ull wd;
            DUP64(wd, wv.x); FMA2(acc[0][0], hv.x, wd); FMA2(acc[0][1], hv.y, wd);
            DUP64(wd, wv.y); FMA2(acc[1][0], hv.x, wd); FMA2(acc[1][1], hv.y, wd);
            DUP64(wd, wv.z); FMA2(acc[2][0], hv.x, wd); FMA2(acc[2][1], hv.y, wd);
            DUP64(wd, wv.w); FMA2(acc[3][0], hv.x, wd); FMA2(acc[3][1], hv.y, wd);
        }

        // all k-splits write partials to smem
        #pragma unroll
        for (int g = 0; g < 4; g++) {
            ull* rp2 = redu + ((ks*4 + g)*4 + jj)*32 + bg*2;
            rp2[0] = acc[g][0];
            rp2[1] = acc[g][1];
        }
        __syncthreads();

        // elementwise LSTM update: one (batch, hidden-unit) cell per thread
        {
            float gi = gxi, gf = gxf, gg = gxg, go = gxo;
            #pragma unroll
            for (int sp = 0; sp < 4; sp++) {
                gi += reduF[((sp*4 + 0)*4 + ejj)*64 + eb];
                gf += reduF[((sp*4 + 1)*4 + ejj)*64 + eb];
                gg += reduF[((sp*4 + 2)*4 + ejj)*64 + eb];
                go += reduF[((sp*4 + 3)*4 + ejj)*64 + eb];
            }
            float ig = 1.f/(1.f + __expf(-gi));
            float fg = 1.f/(1.f + __expf(-gf));
            float og = 1.f/(1.f + __expf(-go));
            float gt = tanhf(gg);
            float cn = fg*creg + ig*gt;
            float hn = og*tanhf(cn);
            float hp = h_s[(j0 + ejj)*64 + eb];
            hn = mv*hn + (1.f - mv)*hp;
            cn = mv*cn + (1.f - mv)*creg;
            creg = cn;
            d_hbuf[wp][d][(j0 + ejj)*64 + eb] = hn;
            out[((size_t)(eb*Tn + t))*OUTW + d*Hh + j0 + ejj] = hn;
        }
        gridbar_dir(d, lgen);
    }
}

// ---------------- launch ----------------
extern "C" void kernel_launch(void* const* d_in, const int* in_sizes, int n_in,
                              void* d_out, int out_size)
{
    const int*   in_word  = (const int*)  d_in[0];
    const int*   in_char  = (const int*)  d_in[1];
    const int*   in_pos   = (const int*)  d_in[2];
    const float* mask     = (const float*)d_in[3];
    const float* emb_word = (const float*)d_in[4];
    const float* emb_char = (const float*)d_in[5];
    const float* emb_pos  = (const float*)d_in[6];
    const float* conv_w   = (const float*)d_in[7];
    const float* conv_b   = (const float*)d_in[8];
    const float* w_ih0    = (const float*)d_in[9];
    const float* w_hh0    = (const float*)d_in[10];
    const float* b0       = (const float*)d_in[11];
    const float* w_ih1    = (const float*)d_in[12];
    const float* w_hh1    = (const float*)d_in[13];
    const float* b1       = (const float*)d_in[14];
    const float* w_ih2    = (const float*)d_in[15];
    const float* w_hh2    = (const float*)d_in[16];
    const float* b2       = (const float*)d_in[17];
    float* out = (float*)d_out;

    cudaFuncSetAttribute(recur_kernel, cudaFuncAttributeMaxDynamicSharedMemorySize, SMEM_REC);

    void *px0, *px1, *px2, *pgx, *pwpad;
    cudaGetSymbolAddress(&px0,  d_x0);
    cudaGetSymbolAddress(&px1,  d_x1);
    cudaGetSymbolAddress(&px2,  d_x2);
    cudaGetSymbolAddress(&pgx,  d_gx);
    cudaGetSymbolAddress(&pwpad, d_wpad);

    // embeddings
    u_kernel<<<CVv, 128>>>(emb_char, conv_w);
    padw_kernel<<<(NW*DP + 255)/256, 256>>>(w_ih0);
    embed_kernel<<<BT, 128>>>(in_word, in_char, in_pos, emb_word, emb_pos, conv_b);

    dim3 ggrid(NW/128, BT/128);

    // layer 0
    gemm_kernel<<<ggrid, 256>>>((const float*)px0, (const float*)pwpad, b0, (float*)pgx);
    barinit_kernel<<<1, 1>>>();
    recur_kernel<<<128, 256, SMEM_REC>>>((const float*)pgx, w_hh0, mask, (float*)px1);

    // layer 1
    gemm_kernel<<<ggrid, 256>>>((const float*)px1, w_ih1, b1, (float*)pgx);
    barinit_kernel<<<1, 1>>>();
    recur_kernel<<<128, 256, SMEM_REC>>>((const float*)pgx, w_hh1, mask, (float*)px2);

    // layer 2
    gemm_kernel<<<ggrid, 256>>>((const float*)px2, w_ih2, b2, (float*)pgx);
    barinit_kernel<<<1, 1>>>();
    recur_kernel<<<128, 256, SMEM_REC>>>((const float*)pgx, w_hh2, mask, out);
}

// round 9
// speedup vs baseline: 1.5261x; 1.2727x over previous
#include <cuda_runtime.h>
#include <cuda_bf16.h>
#include <cstdint>

typedef unsigned long long ull;

// ---------------- problem constants ----------------
#define Bsz   64
#define Tn    256
#define Lc    20
#define WD    300
#define CDm   100
#define PDm   100
#define NF    100
#define CVv   100
#define Hh    256
#define D0r   500
#define DP    512
#define G4    1024
#define NW    2048
#define BT    (Bsz*Tn)
#define OUTW  (2*Hh)

#define DUP64(dst, s)   asm("mov.b64 %0, {%1, %1};" : "=l"(dst) : "r"(__float_as_uint(s)))
#define FMA2(acc, a, b) asm("fma.rn.f32x2 %0, %1, %2, %0;" : "+l"(acc) : "l"(a), "l"(b))
#define ADD2(acc, a)    asm("add.rn.f32x2 %0, %1, %0;" : "+l"(acc) : "l"(a))

// ---------------- scratch (device globals; no runtime alloc) ----------------
__device__ __align__(256) float d_x0[BT*DP];
__device__ __align__(256) float d_x1[BT*OUTW];
__device__ __align__(256) float d_x2[BT*OUTW];
__device__ __align__(256) float d_gx[(size_t)BT*NW];
__device__ __align__(256) float d_wpad[NW*DP];
__device__ float d_U[CVv*3*NF];
__device__ __align__(256) float d_hbuf[2][2][Hh*Bsz];
__device__ __align__(256) __nv_bfloat16 d_Ah[BT*DP];
__device__ __align__(256) __nv_bfloat16 d_Al[BT*DP];
__device__ __align__(256) __nv_bfloat16 d_Wh[NW*DP];
__device__ __align__(256) __nv_bfloat16 d_Wl[NW*DP];
__device__ unsigned g_cnt2[2];
__device__ unsigned g_gen2[2];

// ---------------- ptx helpers (compute_103-safe only) ----------------
__device__ __forceinline__ uint32_t s2u(const void* p){
    uint32_t a;
    asm("{ .reg .u64 t; cvta.to.shared.u64 t, %1; cvt.u32.u64 %0, t; }" : "=r"(a) : "l"(p));
    return a;
}
__device__ __forceinline__ void ldsm4(uint32_t* r, uint32_t addr){
    asm volatile("ldmatrix.sync.aligned.m8n8.x4.shared.b16 {%0,%1,%2,%3}, [%4];"
        : "=r"(r[0]), "=r"(r[1]), "=r"(r[2]), "=r"(r[3]) : "r"(addr));
}
__device__ __forceinline__ void mma16816(float* c, const uint32_t* a, const uint32_t* b){
    asm volatile("mma.sync.aligned.m16n8k16.row.col.f32.bf16.bf16.f32 "
        "{%0,%1,%2,%3}, {%4,%5,%6,%7}, {%8,%9}, {%0,%1,%2,%3};"
        : "+f"(c[0]), "+f"(c[1]), "+f"(c[2]), "+f"(c[3])
        : "r"(a[0]), "r"(a[1]), "r"(a[2]), "r"(a[3]), "r"(b[0]), "r"(b[1]));
}
__device__ __forceinline__ void cpa16(uint32_t dst, const void* src){
    asm volatile("cp.async.cg.shared.global [%0], [%1], 16;" :: "r"(dst), "l"(src) : "memory");
}
#define CP_COMMIT() asm volatile("cp.async.commit_group;" ::: "memory")
#define CP_WAIT0()  asm volatile("cp.async.wait_group 0;" ::: "memory")

// ---------------- fp32 -> bf16 hi/lo split ----------------
__global__ void split_kernel(const float* __restrict__ x,
                             __nv_bfloat16* __restrict__ hi,
                             __nv_bfloat16* __restrict__ lo, int n4)
{
    int i = blockIdx.x*256 + threadIdx.x;
    if (i >= n4) return;
    float4 v = ((const float4*)x)[i];
    float a[4] = {v.x, v.y, v.z, v.w};
    unsigned short hs[4], ls[4];
    #pragma unroll
    for (int j = 0; j < 4; j++) {
        __nv_bfloat16 h = __float2bfloat16(a[j]);
        float r = a[j] - __bfloat162float(h);
        __nv_bfloat16 l = __float2bfloat16(r);
        hs[j] = *(unsigned short*)&h;
        ls[j] = *(unsigned short*)&l;
    }
    ull hv = (ull)hs[0] | ((ull)hs[1]<<16) | ((ull)hs[2]<<32) | ((ull)hs[3]<<48);
    ull lv = (ull)ls[0] | ((ull)ls[1]<<16) | ((ull)ls[2]<<32) | ((ull)ls[3]<<48);
    *(ull*)(hi + 4*(size_t)i) = hv;
    *(ull*)(lo + 4*(size_t)i) = lv;
}

// ---------------- split-bf16 tensor-core GEMM ----------------
// C[16384][2048] = A[16384][512] * W[2048][512]^T + bias, A ~ Ah+Al, W ~ Wh+Wl
// block 128x128, 8 warps (4m x 2n, warp tile 32x64), k-chunk 64, cp.async double buffer.
// smem buffer b at b*65536: {Ah:0, Al:16384, Wh:32768, Wl:49152}, SW128 swizzle.
#define SMEM_GB 131072

__global__ void __launch_bounds__(256) gemm_bf16_kernel(
    const __nv_bfloat16* __restrict__ Ah, const __nv_bfloat16* __restrict__ Al,
    const __nv_bfloat16* __restrict__ Wh, const __nv_bfloat16* __restrict__ Wl,
    const float* __restrict__ bias, float* __restrict__ C)
{
    extern __shared__ __align__(1024) char smem[];
    uint32_t sb = s2u(smem);
    int tid = threadIdx.x, lane = tid & 31, wid = tid >> 5;
    int bm = blockIdx.y*128, bn = blockIdx.x*128;
    int wm = (wid >> 1)*32, wn = (wid & 1)*64;

    const __nv_bfloat16* srcs[4];
    srcs[0] = Ah + (size_t)bm*DP;
    srcs[1] = Al + (size_t)bm*DP;
    srcs[2] = Wh + (size_t)bn*DP;
    srcs[3] = Wl + (size_t)bn*DP;

    // loader coords: row r (0..127) by 2 threads, segs s0..s0+3 (16B units)
    int r  = tid >> 1;
    int s0 = (tid & 1)*4;
    uint32_t dbase = r*128;

    float acc[2][8][4];
    #pragma unroll
    for (int i = 0; i < 2; i++)
        #pragma unroll
        for (int j = 0; j < 8; j++)
            #pragma unroll
            for (int q = 0; q < 4; q++) acc[i][j][q] = 0.f;

    // preload chunk 0
    #pragma unroll
    for (int m = 0; m < 4; m++) {
        const __nv_bfloat16* src = srcs[m] + (size_t)r*DP + s0*8;
        uint32_t d = sb + m*16384 + dbase;
        #pragma unroll
        for (int i = 0; i < 4; i++)
            cpa16(d + (((s0+i)*16) ^ ((r&7)<<4)), src + i*8);
    }
    CP_COMMIT();

    int arow_l = (lane&7) + ((lane&8) ? 8 : 0);
    int akel_l = (lane&16) ? 8 : 0;
    int nrow_l = (lane&7) + ((lane&16) ? 8 : 0);
    int bkel_l = (lane&8) ? 8 : 0;

    for (int ch = 0; ch < 8; ch++) {
        CP_WAIT0();
        __syncthreads();
        if (ch < 7) {
            uint32_t base = sb + ((ch+1)&1)*65536;
            #pragma unroll
            for (int m = 0; m < 4; m++) {
                const __nv_bfloat16* src = srcs[m] + (size_t)r*DP + (ch+1)*64 + s0*8;
                uint32_t d = base + m*16384 + dbase;
                #pragma unroll
                for (int i = 0; i < 4; i++)
                    cpa16(d + (((s0+i)*16) ^ ((r&7)<<4)), src + i*8);
            }
            CP_COMMIT();
        }
        uint32_t bb = sb + (ch&1)*65536;
        #pragma unroll
        for (int s = 0; s < 4; s++) {
            uint32_t a_h[2][4], a_l[2][4];
            #pragma unroll
            for (int mt = 0; mt < 2; mt++) {
                int row = wm + mt*16 + arow_l;
                int kel = s*16 + akel_l;
                uint32_t ad = bb + row*128 + ((kel*2) ^ ((row&7)<<4));
                ldsm4(a_h[mt], ad);
                ldsm4(a_l[mt], ad + 16384);
            }
            uint32_t b_h[8][2], b_l[8][2];
            #pragma unroll
            for (int g = 0; g < 4; g++) {
                int row = wn + g*16 + nrow_l;
                int kel = s*16 + bkel_l;
                uint32_t ad = bb + 32768 + row*128 + ((kel*2) ^ ((row&7)<<4));
                uint32_t t4[4];
                ldsm4(t4, ad);
                b_h[2*g][0] = t4[0]; b_h[2*g][1] = t4[1];
                b_h[2*g+1][0] = t4[2]; b_h[2*g+1][1] = t4[3];
                ldsm4(t4, ad + 16384);
                b_l[2*g][0] = t4[0]; b_l[2*g][1] = t4[1];
                b_l[2*g+1][0] = t4[2]; b_l[2*g+1][1] = t4[3];
            }
            #pragma unroll
            for (int i = 0; i < 2; i++)
                #pragma unroll
                for (int j = 0; j < 8; j++) {
                    mma16816(acc[i][j], a_h[i], b_h[j]);
                    mma16816(acc[i][j], a_h[i], b_l[j]);
                    mma16816(acc[i][j], a_l[i], b_h[j]);
                }
        }
    }

    // epilogue: fragment -> global + bias
    int rr = lane >> 2, cc = (lane & 3)*2;
    #pragma unroll
    for (int i = 0; i < 2; i++) {
        #pragma unroll
        for (int j = 0; j < 8; j++) {
            int row = bm + wm + i*16 + rr;
            int col = bn + wn + j*8 + cc;
            float bx = __ldg(bias + col), by = __ldg(bias + col + 1);
            float2 v0 = make_float2(acc[i][j][0] + bx, acc[i][j][1] + by);
            float2 v1 = make_float2(acc[i][j][2] + bx, acc[i][j][3] + by);
            *(float2*)(C + (size_t)row*NW + col) = v0;
            *(float2*)(C + (size_t)(row+8)*NW + col) = v1;
        }
    }
}

// ---------------- U[v][k][f] ----------------
__global__ void u_kernel(const float* __restrict__ Ec, const float* __restrict__ cw)
{
    int v = blockIdx.x;
    int f = threadIdx.x;
    __shared__ float e[CDm];
    if (f < CDm) e[f] = Ec[v*CDm + f];
    __syncthreads();
    if (f < NF) {
        float a0 = 0.f, a1 = 0.f, a2 = 0.f;
        #pragma unroll 4
        for (int c = 0; c < CDm; c++) {
            float ev = e[c];
            const float* wp = cw + f*(CDm*3) + c*3;
            a0 += ev*wp[0]; a1 += ev*wp[1]; a2 += ev*wp[2];
        }
        d_U[v*300 +       f] = a0;
        d_U[v*300 + 100 + f] = a1;
        d_U[v*300 + 200 + f] = a2;
    }
}

__global__ void padw_kernel(const float* __restrict__ w0)
{
    int idx = blockIdx.x*256 + threadIdx.x;
    if (idx >= NW*DP) return;
    int n = idx >> 9, k = idx & 511;
    d_wpad[idx] = (k < D0r) ? w0[n*D0r + k] : 0.f;
}

__global__ void embed_kernel(const int* __restrict__ word, const int* __restrict__ chars,
                             const int* __restrict__ pos,  const float* __restrict__ Ew,
                             const float* __restrict__ Ep, const float* __restrict__ cb)
{
    int bt  = blockIdx.x;
    int tid = threadIdx.x;
    __shared__ int cs[Lc];
    if (tid < Lc) cs[tid] = chars[bt*Lc + tid];
    int w = word[bt];
    int p = pos[bt];
    float* xrow = d_x0 + (size_t)bt*DP;
    for (int i = tid; i < WD; i += 128)  xrow[i]       = Ew[(size_t)w*WD + i];
    for (int i = tid; i < PDm; i += 128) xrow[400 + i] = Ep[p*PDm + i];
    if (tid < DP - D0r) xrow[D0r + tid] = 0.f;
    __syncthreads();
    if (tid < NF) {
        int f = tid;
        float acc[Lc + 2];
        float bv = cb[f];
        #pragma unroll
        for (int q = 0; q < Lc + 2; q++) acc[q] = bv;
        #pragma unroll
        for (int j = 0; j < Lc; j++) {
            const float* u = d_U + cs[j]*300 + f;
            acc[j + 2] += u[0];
            acc[j + 1] += u[100];
            acc[j    ] += u[200];
        }
        float m = acc[0];
        #pragma unroll
        for (int q = 1; q < Lc + 2; q++) m = fmaxf(m, acc[q]);
        xrow[WD + f] = tanhf(m);
    }
}

// ---------------- barrier ----------------
__global__ void barinit_kernel() { g_cnt2[0] = 0; g_cnt2[1] = 0; g_gen2[0] = 0; g_gen2[1] = 0; }

__device__ __forceinline__ void gridbar_dir(int d, unsigned &lgen)
{
    __syncthreads();
    if (threadIdx.x == 0) {
        __threadfence();
        unsigned v = atomicAdd(&g_cnt2[d], 1);
        if (v == 63) {
            atomicExch(&g_cnt2[d], 0);
            __threadfence();
            atomicExch(&g_gen2[d], lgen + 1);
        } else {
            volatile unsigned* vg = &g_gen2[d];
            while (*vg <= lgen) { }
        }
    }
    lgen++;
    __syncthreads();
}

// ---------------- persistent BiLSTM recurrence ----------------
#define SMEM_REC (65536 + 16384 + 16384)

__global__ void __launch_bounds__(256, 1)
recur_kernel(const float* __restrict__ gx, const float* __restrict__ whh,
             const float* __restrict__ mask, float* __restrict__ out)
{
    extern __shared__ __align__(16) float smemf[];
    float* h_s   = smemf;
    float* w_s   = smemf + 16384;
    ull*   redu  = (ull*)(smemf + 20480);
    float* reduF = (float*)redu;

    int tid = threadIdx.x;
    int d   = blockIdx.x >> 6;
    int blk = blockIdx.x & 63;
    int j0  = blk * 4;

    int jj = tid & 3;
    int bg = (tid >> 2) & 15;
    int ks = tid >> 6;
    int b0 = bg * 4;
    int kbase = ks * 64;

    int eb  = tid & 63;
    int ejj = tid >> 6;

    for (int e = tid; e < 4096; e += 256) {
        int gate = e & 3, jje = (e >> 2) & 3, k = e >> 4;
        w_s[e] = whh[((size_t)d*G4 + gate*Hh + j0 + jje)*Hh + k];
    }
    d_hbuf[1][d][(j0 + ejj)*Bsz + eb] = 0.f;

    float creg = 0.f;
    unsigned lgen = 0;
    gridbar_dir(d, lgen);

    for (int s = 0; s < Tn; s++) {
        int rp = (s & 1) ^ 1;
        int wp = s & 1;
        int t  = d ? (Tn - 1 - s) : s;

        const float* gp = gx + ((size_t)(eb*Tn + t))*NW + d*G4 + j0 + ejj;
        float gxi = __ldg(gp);
        float gxf = __ldg(gp + Hh);
        float gxg = __ldg(gp + 2*Hh);
        float gxo = __ldg(gp + 3*Hh);
        float mv  = __ldg(mask + eb*Tn + t);

        const float* hsrc = d_hbuf[rp][d];
        #pragma unroll
        for (int i = 0; i < 16; i++) {
            int idx = (i*256 + tid)*4;
            *(float4*)(h_s + idx) = __ldcg((const float4*)(hsrc + idx));
        }
        __syncthreads();

        ull acc[4][2];
        #pragma unroll
        for (int g = 0; g < 4; g++) { acc[g][0] = 0ULL; acc[g][1] = 0ULL; }

        #pragma unroll 4
        for (int kk = 0; kk < 64; kk++) {
            int k = kbase + kk;
            ulonglong2 hv = *(const ulonglong2*)(h_s + k*64 + b0);
            float4 wv = *(const float4*)(w_s + k*16 + jj*4);
            ull wd;
            DUP64(wd, wv.x); FMA2(acc[0][0], hv.x, wd); FMA2(acc[0][1], hv.y, wd);
            DUP64(wd, wv.y); FMA2(acc[1][0], hv.x, wd); FMA2(acc[1][1], hv.y, wd);
            DUP64(wd, wv.z); FMA2(acc[2][0], hv.x, wd); FMA2(acc[2][1], hv.y, wd);
            DUP64(wd, wv.w); FMA2(acc[3][0], hv.x, wd); FMA2(acc[3][1], hv.y, wd);
        }

        #pragma unroll
        for (int g = 0; g < 4; g++) {
            ull* rp2 = redu + ((ks*4 + g)*4 + jj)*32 + bg*2;
            rp2[0] = acc[g][0];
            rp2[1] = acc[g][1];
        }
        __syncthreads();

        {
            float gi = gxi, gf = gxf, gg = gxg, go = gxo;
            #pragma unroll
            for (int sp = 0; sp < 4; sp++) {
                gi += reduF[((sp*4 + 0)*4 + ejj)*64 + eb];
                gf += reduF[((sp*4 + 1)*4 + ejj)*64 + eb];
                gg += reduF[((sp*4 + 2)*4 + ejj)*64 + eb];
                go += reduF[((sp*4 + 3)*4 + ejj)*64 + eb];
            }
            float ig = 1.f/(1.f + __expf(-gi));
            float fg = 1.f/(1.f + __expf(-gf));
            float og = 1.f/(1.f + __expf(-go));
            float gt = tanhf(gg);
            float cn = fg*creg + ig*gt;
            float hn = og*tanhf(cn);
            float hp = h_s[(j0 + ejj)*64 + eb];
            hn = mv*hn + (1.f - mv)*hp;
            cn = mv*cn + (1.f - mv)*creg;
            creg = cn;
            d_hbuf[wp][d][(j0 + ejj)*64 + eb] = hn;
            out[((size_t)(eb*Tn + t))*OUTW + d*Hh + j0 + ejj] = hn;
        }
        gridbar_dir(d, lgen);
    }
}

// ---------------- launch ----------------
extern "C" void kernel_launch(void* const* d_in, const int* in_sizes, int n_in,
                              void* d_out, int out_size)
{
    const int*   in_word  = (const int*)  d_in[0];
    const int*   in_char  = (const int*)  d_in[1];
    const int*   in_pos   = (const int*)  d_in[2];
    const float* mask     = (const float*)d_in[3];
    const float* emb_word = (const float*)d_in[4];
    const float* emb_char = (const float*)d_in[5];
    const float* emb_pos  = (const float*)d_in[6];
    const float* conv_w   = (const float*)d_in[7];
    const float* conv_b   = (const float*)d_in[8];
    const float* w_ih0    = (const float*)d_in[9];
    const float* w_hh0    = (const float*)d_in[10];
    const float* b0       = (const float*)d_in[11];
    const float* w_ih1    = (const float*)d_in[12];
    const float* w_hh1    = (const float*)d_in[13];
    const float* b1       = (const float*)d_in[14];
    const float* w_ih2    = (const float*)d_in[15];
    const float* w_hh2    = (const float*)d_in[16];
    const float* b2       = (const float*)d_in[17];
    float* out = (float*)d_out;

    cudaFuncSetAttribute(recur_kernel, cudaFuncAttributeMaxDynamicSharedMemorySize, SMEM_REC);
    cudaFuncSetAttribute(gemm_bf16_kernel, cudaFuncAttributeMaxDynamicSharedMemorySize, SMEM_GB);

    void *px0, *px1, *px2, *pgx, *pwpad, *pAh, *pAl, *pWh, *pWl;
    cudaGetSymbolAddress(&px0,  d_x0);
    cudaGetSymbolAddress(&px1,  d_x1);
    cudaGetSymbolAddress(&px2,  d_x2);
    cudaGetSymbolAddress(&pgx,  d_gx);
    cudaGetSymbolAddress(&pwpad, d_wpad);
    cudaGetSymbolAddress(&pAh, d_Ah);
    cudaGetSymbolAddress(&pAl, d_Al);
    cudaGetSymbolAddress(&pWh, d_Wh);
    cudaGetSymbolAddress(&pWl, d_Wl);

    u_kernel<<<CVv, 128>>>(emb_char, conv_w);
    padw_kernel<<<(NW*DP + 255)/256, 256>>>(w_ih0);
    embed_kernel<<<BT, 128>>>(in_word, in_char, in_pos, emb_word, emb_pos, conv_b);

    dim3 ggrid(NW/128, BT/128);
    const int nA4 = BT*DP/4;        // 2.1M float4
    const int nW4 = NW*DP/4;

    // ---- layer 0 ----
    split_kernel<<<(nA4 + 255)/256, 256>>>((const float*)px0,
        (__nv_bfloat16*)pAh, (__nv_bfloat16*)pAl, nA4);
    split_kernel<<<(nW4 + 255)/256, 256>>>((const float*)pwpad,
        (__nv_bfloat16*)pWh, (__nv_bfloat16*)pWl, nW4);
    gemm_bf16_kernel<<<ggrid, 256, SMEM_GB>>>((const __nv_bfloat16*)pAh, (const __nv_bfloat16*)pAl,
        (const __nv_bfloat16*)pWh, (const __nv_bfloat16*)pWl, b0, (float*)pgx);
    barinit_kernel<<<1, 1>>>();
    recur_kernel<<<128, 256, SMEM_REC>>>((const float*)pgx, w_hh0, mask, (float*)px1);

    // ---- layer 1 ----
    split_kernel<<<(nA4 + 255)/256, 256>>>((const float*)px1,
        (__nv_bfloat16*)pAh, (__nv_bfloat16*)pAl, nA4);
    split_kernel<<<(nW4 + 255)/256, 256>>>(w_ih1,
        (__nv_bfloat16*)pWh, (__nv_bfloat16*)pWl, nW4);
    gemm_bf16_kernel<<<ggrid, 256, SMEM_GB>>>((const __nv_bfloat16*)pAh, (const __nv_bfloat16*)pAl,
        (const __nv_bfloat16*)pWh, (const __nv_bfloat16*)pWl, b1, (float*)pgx);
    barinit_kernel<<<1, 1>>>();
    recur_kernel<<<128, 256, SMEM_REC>>>((const float*)pgx, w_hh1, mask, (float*)px2);

    // ---- layer 2 ----
    split_kernel<<<(nA4 + 255)/256, 256>>>((const float*)px2,
        (__nv_bfloat16*)pAh, (__nv_bfloat16*)pAl, nA4);
    split_kernel<<<(nW4 + 255)/256, 256>>>(w_ih2,
        (__nv_bfloat16*)pWh, (__nv_bfloat16*)pWl, nW4);
    gemm_bf16_kernel<<<ggrid, 256, SMEM_GB>>>((const __nv_bfloat16*)pAh, (const __nv_bfloat16*)pAl,
        (const __nv_bfloat16*)pWh, (const __nv_bfloat16*)pWl, b2, (float*)pgx);
    barinit_kernel<<<1, 1>>>();
    recur_kernel<<<128, 256, SMEM_REC>>>((const float*)pgx, w_hh2, mask, out);
}